// round 8
// baseline (speedup 1.0000x reference)
#include <cuda_runtime.h>

#define TT 2048
#define BB 4096
#define NTH 512
#define NCTA 128

typedef unsigned long long u64;

static __device__ __forceinline__ u64 pk2(float x, float y){
    u64 r; asm("mov.b64 %0,{%1,%2};" : "=l"(r) : "f"(x), "f"(y)); return r;
}
static __device__ __forceinline__ void up2(u64 v, float &x, float &y){
    asm("mov.b64 {%0,%1},%2;" : "=f"(x), "=f"(y) : "l"(v));
}
static __device__ __forceinline__ u64 swp2(u64 v){   // (lo,hi) -> (hi,lo)
    float x, y; up2(v, x, y); return pk2(y, x);
}
static __device__ __forceinline__ u64 fma2(u64 a, u64 b, u64 c){
    u64 d; asm("fma.rn.f32x2 %0,%1,%2,%3;" : "=l"(d) : "l"(a), "l"(b), "l"(c)); return d;
}
static __device__ __forceinline__ u64 add2(u64 a, u64 b){
    u64 d; asm("add.rn.f32x2 %0,%1,%2;" : "=l"(d) : "l"(a), "l"(b)); return d;
}
static __device__ __forceinline__ u64 mul2(u64 a, u64 b){
    u64 d; asm("mul.rn.f32x2 %0,%1,%2;" : "=l"(d) : "l"(a), "l"(b)); return d;
}
static __device__ __forceinline__ u64 relu2(u64 a){
    float x, y; up2(a, x, y);
    return pk2(fmaxf(x, 0.f), fmaxf(y, 0.f));
}
static __device__ __forceinline__ float pick4(float a, float b, float c, float d, int s){
    float x = (s & 1) ? b : a;
    float y = (s & 1) ? d : c;
    return (s & 2) ? y : x;
}
static __device__ __forceinline__ void pair_bar(int pair){
    asm volatile("bar.sync %0, 64;" :: "r"(pair + 1) : "memory");
}

__global__ __launch_bounds__(NTH, 1)
void garch_pinn_kernel(
    const float* __restrict__ returns, const float* __restrict__ log_rv,
    const float* __restrict__ omega_p, const float* __restrict__ beta_p,
    const float* __restrict__ tau1_p, const float* __restrict__ tau2_p,
    const float* __restrict__ gamma_p, const float* __restrict__ xi_p,
    const float* __restrict__ phi_p, const float* __restrict__ d1_p,
    const float* __restrict__ d2_p, const float* __restrict__ mu_p,
    const float* __restrict__ W1, const float* __restrict__ b1,
    const float* __restrict__ W2, const float* __restrict__ b2,
    const float* __restrict__ W3, const float* __restrict__ b3_p,
    float* __restrict__ out)
{
    // per-warp h1 half-tile (warp-private): sh1[w][i2] = 4 chains' h at row ro*32+i2
    __shared__ __align__(16) float4 sh1[16][32];             // 8 KB
    // partial-accumulator exchange, double-buffered: [buf][pair][ro][lane][4]
    __shared__ __align__(16) u64 pbuf[2][8][2][32][4];       // 32 KB
    // output staging: [pair][arr*4+chain][9] (flush every 8 steps)
    __shared__ float obuf[8][16][9];                         // 4.5 KB

    const int tid = threadIdx.x;
    const int w = tid >> 5;
    const int l = tid & 31;
    const int pair = w >> 1;
    const int ro = w & 1;           // 0: i in [0,32), 1: i in [32,64)

    // ---- W2 half in registers: lane owns output cols (l, l+32), rows ro*32+[0,32) ----
    u64 wreg[32];
    #pragma unroll
    for (int i2 = 0; i2 < 32; i2++) {
        const int i = ro * 32 + i2;
        wreg[i2] = pk2(W2[i * 64 + l], W2[i * 64 + l + 32]);
    }

    // layer-1: this lane computes exactly one h1 row
    const int row = ro * 32 + l;
    const float w1r0 = W1[0 * 64 + row], w1r1 = W1[1 * 64 + row], w1r2 = W1[2 * 64 + row];
    const float b1r = b1[row];
    const u64 w3pair = pk2(W3[l], W3[l + 32]);
    const u64 seed = ro == 0 ? pk2(b2[l], b2[l + 32]) : 0ull;  // b2 folded into low half

    const float omega = *omega_p, beta = *beta_p, tau1 = *tau1_p, tau2 = *tau2_p;
    const float gam = *gamma_p, xi = *xi_p, phi = *phi_p;
    const float d1 = *d1_p, d2 = *d2_p, mu = *mu_p, b3 = *b3_p;

    // this pair's 4 batch chains (state kept redundantly in both warps)
    const long bg = (long)blockIdx.x * 32 + pair * 4;
    const float* rp = returns + bg * TT;
    const float* lp = log_rv + bg * TT;
    const long BT = (long)BB * TT;

    float lh[4];
    #pragma unroll
    for (int b = 0; b < 4; b++) lh[b] = lp[b * TT];   // log(mean(exp(lrv0))) == lrv0

    u64 (*pme)[4]  = &pbuf[0][pair][ro][0];
    u64 (*poth)[4] = &pbuf[0][pair][1 - ro][0];
    const long pstride = 8 * 2 * 32 * 4;              // u64 elems per buffer
    float* obw = &obuf[pair][0][0];

    __syncthreads();

    for (int t = 0; t < TT; t++) {
        // ---- inputs (warp-uniform loads, L1-resident lines) ----
        float rcur[4], lcur[4];
        #pragma unroll
        for (int b = 0; b < 4; b++) { rcur[b] = rp[b * TT + t]; lcur[b] = lp[b * TT + t]; }

        // ---- measurement (redundant in both warps of the pair) ----
        float z[4], u[4], z2m1[4];
        #pragma unroll
        for (int b = 0; b < 4; b++) {
            float e = __expf(-0.5f * lh[b]);
            z[b] = (rcur[b] - mu) * e;
            z2m1[b] = z[b] * z[b] - 1.0f;
            float s = xi + phi * lh[b] + d1 * z[b] + d2 * z2m1[b];
            u[b] = lcur[b] - s;              // log_x == lcur exactly
        }

        // ---- layer 1: one row per lane, 4 chains ----
        float va[4];
        #pragma unroll
        for (int b = 0; b < 4; b++) {
            float t0 = fmaf(w1r0, lh[b], b1r);
            t0 = fmaf(w1r1, z[b], t0);
            t0 = fmaf(w1r2, u[b], t0);
            va[b] = fmaxf(t0, 0.0f);
        }
        __syncwarp();
        sh1[w][l] = make_float4(va[0], va[1], va[2], va[3]);

        // stage reduction-independent outputs (z,u,log_x) while smem settles
        // warp A (ro=0): q=0..7 -> arr 0(enh later),1(lx); warp B: q=8..15 -> arr 2(z),3(u)
        if (ro == 1 && l < 8) {
            const int bsel = l & 3;
            float v_z = pick4(z[0], z[1], z[2], z[3], bsel);
            float v_u = pick4(u[0], u[1], u[2], u[3], bsel);
            obw[(8 + l) * 9 + (t & 7)] = (l < 4) ? v_z : v_u;
        }
        if (ro == 0 && l >= 4 && l < 8) {
            const int bsel = l & 3;
            obw[l * 9 + (t & 7)] = pick4(lcur[0], lcur[1], lcur[2], lcur[3], bsel);  // arr1 = log_x
        }
        __syncwarp();

        // ---- layer 2 over own i-half: W2 in regs, h broadcast from warp-private smem ----
        const ulonglong2* hA = reinterpret_cast<const ulonglong2*>(&sh1[w][0]);
        u64 aA = seed, aB = seed, aC = seed, aD = seed;
        #pragma unroll
        for (int i2 = 0; i2 < 32; i2++) {
            ulonglong2 P = hA[i2];           // P.x=(b0,b1) P.y=(b2,b3), broadcast
            u64 s01 = swp2(P.x), s23 = swp2(P.y);
            aA = fma2(P.x, wreg[i2], aA);
            aB = fma2(s01, wreg[i2], aB);
            aC = fma2(P.y, wreg[i2], aC);
            aD = fma2(s23, wreg[i2], aD);
        }

        // ---- exchange partials with the paired warp (double-buffered, 1 bar) ----
        const long boff = (t & 1) ? pstride : 0;
        {
            ulonglong2* dst = reinterpret_cast<ulonglong2*>(&pme[l][0] + boff);
            dst[0] = make_ulonglong2(aA, aB);
            dst[1] = make_ulonglong2(aC, aD);
        }
        pair_bar(pair);
        u64 accA, accB, accC, accD;
        {
            const ulonglong2* src = reinterpret_cast<const ulonglong2*>(&poth[l][0] + boff);
            ulonglong2 o01 = src[0], o23 = src[1];
            // deterministic order: low-half (seeded) + high-half
            if (ro == 0) {
                accA = add2(aA, o01.x); accB = add2(aB, o01.y);
                accC = add2(aC, o23.x); accD = add2(aD, o23.y);
            } else {
                accA = add2(o01.x, aA); accB = add2(o01.y, aB);
                accC = add2(o23.x, aC); accD = add2(o23.y, aD);
            }
        }

        // ---- layer 3: relu + W3 dot + swapped-component reassembly ----
        u64 ptA = mul2(relu2(accA), w3pair);   // (c[l][b0], c[l32][b1])
        u64 ptB = mul2(relu2(accB), w3pair);   // (c[l][b1], c[l32][b0])
        u64 ptC = mul2(relu2(accC), w3pair);
        u64 ptD = mul2(relu2(accD), w3pair);
        u64 pair01 = add2(ptA, swp2(ptB));     // (b0 part, b1 part)
        u64 pair23 = add2(ptC, swp2(ptD));

        // warp all-reduce (both warps redundantly -> both get tot[4], no 2nd bar)
        #pragma unroll
        for (int s = 16; s > 0; s >>= 1) {
            pair01 = add2(pair01, __shfl_xor_sync(0xffffffffu, pair01, s));
            pair23 = add2(pair23, __shfl_xor_sync(0xffffffffu, pair23, s));
        }
        float tot[4];
        up2(pair01, tot[0], tot[1]);
        up2(pair23, tot[2], tot[3]);

        float enh[4];
        #pragma unroll
        for (int b = 0; b < 4; b++)
            enh[b] = fmaf(0.01f, tot[b] + b3, lh[b]);

        // stage enh (warp A lanes 0..3)
        if (ro == 0 && l < 4) obw[l * 9 + (t & 7)] = enh[l];

        // ---- GARCH recurrence (redundant in both warps, identical order) ----
        #pragma unroll
        for (int b = 0; b < 4; b++) {
            float nl = fmaf(beta, enh[b], omega);
            nl = fmaf(tau1, z[b], nl);
            nl = fmaf(tau2, z2m1[b], nl);
            lh[b] = fmaf(gam, u[b], nl);
        }

        // ---- flush every 8 steps: 64 elems/warp, 2 per lane ----
        if ((t & 7) == 7) {
            __syncwarp();
            const int t0 = t - 7;
            #pragma unroll
            for (int e = l; e < 64; e += 32) {
                const int q = ro * 8 + (e >> 3);      // staging row
                const int col = e & 7;
                const int arr = q >> 2, bsel = q & 3;
                out[(long)arr * BT + (bg + bsel) * TT + t0 + col] = obw[q * 9 + col];
            }
            __syncwarp();
        }
    }
}

extern "C" void kernel_launch(void* const* d_in, const int* in_sizes, int n_in,
                              void* d_out, int out_size)
{
    garch_pinn_kernel<<<NCTA, NTH>>>(
        (const float*)d_in[0],  (const float*)d_in[1],
        (const float*)d_in[2],  (const float*)d_in[3],
        (const float*)d_in[4],  (const float*)d_in[5],
        (const float*)d_in[6],  (const float*)d_in[7],
        (const float*)d_in[8],  (const float*)d_in[9],
        (const float*)d_in[10], (const float*)d_in[11],
        (const float*)d_in[12], (const float*)d_in[13],
        (const float*)d_in[14], (const float*)d_in[15],
        (const float*)d_in[16], (const float*)d_in[17],
        (float*)d_out);
}

// round 9
// speedup vs baseline: 1.2564x; 1.2564x over previous
#include <cuda_runtime.h>

#define TT 2048
#define BB 4096
#define NTH 256
#define NCTA 128

typedef unsigned long long u64;

static __device__ __forceinline__ u64 pk2(float x, float y){
    u64 r; asm("mov.b64 %0,{%1,%2};" : "=l"(r) : "f"(x), "f"(y)); return r;
}
static __device__ __forceinline__ void up2(u64 v, float &x, float &y){
    asm("mov.b64 {%0,%1},%2;" : "=f"(x), "=f"(y) : "l"(v));
}
static __device__ __forceinline__ u64 swp2(u64 v){   // (lo,hi) -> (hi,lo)
    float x, y; up2(v, x, y); return pk2(y, x);
}
static __device__ __forceinline__ u64 fma2(u64 a, u64 b, u64 c){
    u64 d; asm("fma.rn.f32x2 %0,%1,%2,%3;" : "=l"(d) : "l"(a), "l"(b), "l"(c)); return d;
}
static __device__ __forceinline__ u64 add2(u64 a, u64 b){
    u64 d; asm("add.rn.f32x2 %0,%1,%2;" : "=l"(d) : "l"(a), "l"(b)); return d;
}
static __device__ __forceinline__ u64 mul2(u64 a, u64 b){
    u64 d; asm("mul.rn.f32x2 %0,%1,%2;" : "=l"(d) : "l"(a), "l"(b)); return d;
}
static __device__ __forceinline__ u64 relu2(u64 a){
    float x, y; up2(a, x, y);
    return pk2(fmaxf(x, 0.f), fmaxf(y, 0.f));
}
static __device__ __forceinline__ float pick4(float a, float b, float c, float d, int s){
    float x = (s & 1) ? b : a;
    float y = (s & 1) ? d : c;
    return (s & 2) ? y : x;
}

__global__ __launch_bounds__(NTH, 1)
void garch_pinn_kernel(
    const float* __restrict__ returns, const float* __restrict__ log_rv,
    const float* __restrict__ omega_p, const float* __restrict__ beta_p,
    const float* __restrict__ tau1_p, const float* __restrict__ tau2_p,
    const float* __restrict__ gamma_p, const float* __restrict__ xi_p,
    const float* __restrict__ phi_p, const float* __restrict__ d1_p,
    const float* __restrict__ d2_p, const float* __restrict__ mu_p,
    const float* __restrict__ W1, const float* __restrict__ b1,
    const float* __restrict__ W2, const float* __restrict__ b2,
    const float* __restrict__ W3, const float* __restrict__ b3_p,
    float* __restrict__ out)
{
    // per-warp h1 tile, natural batch pairs: sA[i] = h[i][b0..b3]; warp-private
    __shared__ __align__(16) float4 sh1[8][64];
    // per-warp output staging (warp-private): [warp][arr*4+b][33]
    __shared__ float obuf[8][16][33];

    const int tid = threadIdx.x;
    const int w = tid >> 5;
    const int l = tid & 31;
    const int hf = l >> 4;       // i-half this lane accumulates: [32*hf, 32*hf+32)
    const int c  = l & 15;       // lane owns output cols c, c+16, c+32, c+48

    // ---- W2 half-rows in registers: 32 i × 2 col-pairs = 128 regs ----
    u64 w0r[32], w1r[32];
    #pragma unroll
    for (int j = 0; j < 32; j++) {
        const int i = hf * 32 + j;
        w0r[j] = pk2(W2[i * 64 + c],      W2[i * 64 + c + 32]);
        w1r[j] = pk2(W2[i * 64 + c + 16], W2[i * 64 + c + 48]);
    }

    // layer-1 constants: lane computes h1 rows l and l+32 (full rows, as before)
    const float w1a0 = W1[0 * 64 + l],      w1a1 = W1[1 * 64 + l],      w1a2 = W1[2 * 64 + l];
    const float w1b0 = W1[0 * 64 + l + 32], w1b1 = W1[1 * 64 + l + 32], w1b2 = W1[2 * 64 + l + 32];
    const float b1a = b1[l], b1b = b1[l + 32];
    // layer-3 weights for owned cols
    const u64 w3p0 = pk2(W3[c],      W3[c + 32]);
    const u64 w3p1 = pk2(W3[c + 16], W3[c + 48]);
    // b2 seeded once (half 0 only)
    const u64 sd0 = hf == 0 ? pk2(b2[c],      b2[c + 32]) : 0ull;
    const u64 sd1 = hf == 0 ? pk2(b2[c + 16], b2[c + 48]) : 0ull;

    const float omega = *omega_p, beta = *beta_p, tau1 = *tau1_p, tau2 = *tau2_p;
    const float gam = *gamma_p, xi = *xi_p, phi = *phi_p;
    const float d1 = *d1_p, d2 = *d2_p, mu = *mu_p, b3 = *b3_p;

    // this warp's 4 batch chains
    const long bg = (long)blockIdx.x * 32 + w * 4;
    const float* rp = returns + bg * TT;
    const float* lp = log_rv + bg * TT;
    const long BT = (long)BB * TT;

    float lh[4];
    #pragma unroll
    for (int b = 0; b < 4; b++) lh[b] = lp[b * TT];   // log(mean(exp(lrv0))) == lrv0

    float4* sA = &sh1[w][0];
    const ulonglong2* hA = reinterpret_cast<const ulonglong2*>(sA) + hf * 32;
    float* obw = &obuf[w][0][0];

    for (int t = 0; t < TT; t++) {
        // ---- inputs (warp-uniform, L1-resident; independent of carried lh) ----
        float rcur[4], lcur[4];
        #pragma unroll
        for (int b = 0; b < 4; b++) { rcur[b] = rp[b * TT + t]; lcur[b] = lp[b * TT + t]; }

        // ---- measurement (redundant in every lane) ----
        float z[4], u[4], z2m1[4];
        #pragma unroll
        for (int b = 0; b < 4; b++) {
            float e = __expf(-0.5f * lh[b]);
            z[b] = (rcur[b] - mu) * e;
            z2m1[b] = z[b] * z[b] - 1.0f;
            float s = xi + phi * lh[b] + d1 * z[b] + d2 * z2m1[b];
            u[b] = lcur[b] - s;              // log_x == lcur exactly
        }

        // ---- layer 1: rows l and l+32, all 4 chains ----
        float va[4], vb[4];
        #pragma unroll
        for (int b = 0; b < 4; b++) {
            float t0 = fmaf(w1a0, lh[b], b1a);
            t0 = fmaf(w1a1, z[b], t0);
            t0 = fmaf(w1a2, u[b], t0);
            va[b] = fmaxf(t0, 0.0f);
            float t1 = fmaf(w1b0, lh[b], b1b);
            t1 = fmaf(w1b1, z[b], t1);
            t1 = fmaf(w1b2, u[b], t1);
            vb[b] = fmaxf(t1, 0.0f);
        }
        // warp-private tile; same-warp program order makes this safe w/o sync
        sA[l]      = make_float4(va[0], va[1], va[2], va[3]);
        sA[l + 32] = make_float4(vb[0], vb[1], vb[2], vb[3]);

        // stage reduction-independent outputs (lanes 4..15): arr 1=lx, 2=z, 3=u
        {
            const int bsel = l & 3;
            float v_lx = pick4(lcur[0], lcur[1], lcur[2], lcur[3], bsel);
            float v_z  = pick4(z[0], z[1], z[2], z[3], bsel);
            float v_u  = pick4(u[0], u[1], u[2], u[3], bsel);
            float v = pick4(v_lx, v_lx, v_z, v_u, l >> 2);
            if (l >= 4 && l < 16) obw[l * 33 + (t & 31)] = v;
        }

        // ---- layer 2: each half-warp accumulates its 32 i's over 4 owned cols ----
        // combos: A=(b0|c.., b1|c+32..) B=swapped C=(b2,b3) D=swapped
        u64 aA0 = sd0, aB0 = sd0, aC0 = sd0, aD0 = sd0;
        u64 aA1 = sd1, aB1 = sd1, aC1 = sd1, aD1 = sd1;
        #pragma unroll
        for (int j = 0; j < 32; j++) {
            ulonglong2 P = hA[j];            // h[i][b0..b3], i = hf*32+j
            u64 s01 = swp2(P.x), s23 = swp2(P.y);
            aA0 = fma2(P.x, w0r[j], aA0);  aA1 = fma2(P.x, w1r[j], aA1);
            aB0 = fma2(s01, w0r[j], aB0);  aB1 = fma2(s01, w1r[j], aB1);
            aC0 = fma2(P.y, w0r[j], aC0);  aC1 = fma2(P.y, w1r[j], aC1);
            aD0 = fma2(s23, w0r[j], aD0);  aD1 = fma2(s23, w1r[j], aD1);
        }

        // ---- merge i-halves across lane^16 (relu AFTER full sum; fixed order) ----
        #define MERGE16(a) { u64 o = __shfl_xor_sync(0xffffffffu, (a), 16); \
                             (a) = hf ? add2(o, (a)) : add2((a), o); }
        MERGE16(aA0) MERGE16(aA1) MERGE16(aB0) MERGE16(aB1)
        MERGE16(aC0) MERGE16(aC1) MERGE16(aD0) MERGE16(aD1)
        #undef MERGE16

        // ---- layer 3: relu + W3 dot over 4 owned cols, reassemble batch pairs ----
        u64 ptA = fma2(relu2(aA1), w3p1, mul2(relu2(aA0), w3p0));  // (b0|{c,c16}, b1|{c32,c48})
        u64 ptB = fma2(relu2(aB1), w3p1, mul2(relu2(aB0), w3p0));  // (b1|.., b0|..)
        u64 ptC = fma2(relu2(aC1), w3p1, mul2(relu2(aC0), w3p0));
        u64 ptD = fma2(relu2(aD1), w3p1, mul2(relu2(aD0), w3p0));
        u64 pair01 = add2(ptA, swp2(ptB));     // (b0 part, b1 part) over 4 cols
        u64 pair23 = add2(ptC, swp2(ptD));

        // 4-level reduce over c (lanes l and l+16 hold identical values)
        #pragma unroll
        for (int s = 8; s > 0; s >>= 1) {
            pair01 = add2(pair01, __shfl_xor_sync(0xffffffffu, pair01, s));
            pair23 = add2(pair23, __shfl_xor_sync(0xffffffffu, pair23, s));
        }
        float tot[4];
        up2(pair01, tot[0], tot[1]);
        up2(pair23, tot[2], tot[3]);

        float enh[4];
        #pragma unroll
        for (int b = 0; b < 4; b++)
            enh[b] = fmaf(0.01f, tot[b] + b3, lh[b]);

        if (l < 4) obw[l * 33 + (t & 31)] = enh[l];

        // ---- GARCH recurrence ----
        #pragma unroll
        for (int b = 0; b < 4; b++) {
            float nl = fmaf(beta, enh[b], omega);
            nl = fmaf(tau1, z[b], nl);
            nl = fmaf(tau2, z2m1[b], nl);
            lh[b] = fmaf(gam, u[b], nl);
        }

        // ---- coalesced flush every 32 steps (warp-private buffer) ----
        if ((t & 31) == 31) {
            const int t0 = t - 31;
            #pragma unroll
            for (int q = 0; q < 16; q++) {
                const int arr = q >> 2, bsel = q & 3;
                out[(long)arr * BT + (bg + bsel) * TT + t0 + l] = obw[q * 33 + l];
            }
        }
    }
}

extern "C" void kernel_launch(void* const* d_in, const int* in_sizes, int n_in,
                              void* d_out, int out_size)
{
    garch_pinn_kernel<<<NCTA, NTH>>>(
        (const float*)d_in[0],  (const float*)d_in[1],
        (const float*)d_in[2],  (const float*)d_in[3],
        (const float*)d_in[4],  (const float*)d_in[5],
        (const float*)d_in[6],  (const float*)d_in[7],
        (const float*)d_in[8],  (const float*)d_in[9],
        (const float*)d_in[10], (const float*)d_in[11],
        (const float*)d_in[12], (const float*)d_in[13],
        (const float*)d_in[14], (const float*)d_in[15],
        (const float*)d_in[16], (const float*)d_in[17],
        (float*)d_out);
}

// round 11
// speedup vs baseline: 2.3793x; 1.8936x over previous
#include <cuda_runtime.h>
#include <cuda_bf16.h>

#define TT 2048
#define BB 4096
#define NTH 256
#define NCTA 128

typedef unsigned long long u64;
typedef unsigned int u32;
typedef unsigned short u16;

static __device__ __forceinline__ u64 pk2(float x, float y){
    u64 r; asm("mov.b64 %0,{%1,%2};" : "=l"(r) : "f"(x), "f"(y)); return r;
}
static __device__ __forceinline__ void up2(u64 v, float &x, float &y){
    asm("mov.b64 {%0,%1},%2;" : "=f"(x), "=f"(y) : "l"(v));
}
static __device__ __forceinline__ u64 add2(u64 a, u64 b){
    u64 d; asm("add.rn.f32x2 %0,%1,%2;" : "=l"(d) : "l"(a), "l"(b)); return d;
}
static __device__ __forceinline__ float pick4(float a, float b, float c, float d, int s){
    float x = (s & 1) ? b : a;
    float y = (s & 1) ? d : c;
    return (s & 2) ? y : x;
}
static __device__ __forceinline__ u32 bfpack(float lo, float hi){
    u32 r; asm("cvt.rn.bf16x2.f32 %0, %1, %2;" : "=r"(r) : "f"(hi), "f"(lo)); return r;
}
static __device__ __forceinline__ u16 bf1(float x){
    __nv_bfloat16 b = __float2bfloat16(x);
    return *reinterpret_cast<u16*>(&b);
}
// D(16x8,f32) += A(16x16,bf16 row) * B(16x8,bf16 col)
static __device__ __forceinline__ void mma16816(
    float &c0, float &c1, float &c2, float &c3,
    u32 a0, u32 a1, u32 a2, u32 a3, u32 b0, u32 b1)
{
    asm("mma.sync.aligned.m16n8k16.row.col.f32.bf16.bf16.f32 "
        "{%0,%1,%2,%3},{%4,%5,%6,%7},{%8,%9},{%0,%1,%2,%3};"
        : "+f"(c0), "+f"(c1), "+f"(c2), "+f"(c3)
        : "r"(a0), "r"(a1), "r"(a2), "r"(a3), "r"(b0), "r"(b1));
}

__global__ __launch_bounds__(NTH, 1)
void garch_pinn_kernel(
    const float* __restrict__ returns, const float* __restrict__ log_rv,
    const float* __restrict__ omega_p, const float* __restrict__ beta_p,
    const float* __restrict__ tau1_p, const float* __restrict__ tau2_p,
    const float* __restrict__ gamma_p, const float* __restrict__ xi_p,
    const float* __restrict__ phi_p, const float* __restrict__ d1_p,
    const float* __restrict__ d2_p, const float* __restrict__ mu_p,
    const float* __restrict__ W1, const float* __restrict__ b1,
    const float* __restrict__ W2, const float* __restrict__ b2,
    const float* __restrict__ W3, const float* __restrict__ b3_p,
    float* __restrict__ out)
{
    // bf16 h tile per warp: [chain][i], row padded to 80 u16 (160 B) for
    // conflict-free strided LDS.32 (row banks 40c + k/2).
    __shared__ u16 hsm[8][4][80];                     // 5 KB
    // per-warp output staging: [warp][arr*4+b][33]
    __shared__ float obuf[8][16][33];

    const int tid = threadIdx.x;
    const int w = tid >> 5;
    const int l = tid & 31;
    const int r = l >> 2;          // mma fragment row group
    const int kq = (l & 3) * 2;    // mma fragment k / col pair base

    // ---- A fragments (A[m][k] = W2[k][m]) preloaded, 4 mt x 4 kt x 4 regs ----
    u32 afr[4][4][4];
    #pragma unroll
    for (int mt = 0; mt < 4; mt++) {
        #pragma unroll
        for (int kt = 0; kt < 4; kt++) {
            const int m0 = 16 * mt + r, k0 = 16 * kt + kq;
            afr[mt][kt][0] = bfpack(W2[k0 * 64 + m0],           W2[(k0 + 1) * 64 + m0]);
            afr[mt][kt][1] = bfpack(W2[k0 * 64 + m0 + 8],       W2[(k0 + 1) * 64 + m0 + 8]);
            afr[mt][kt][2] = bfpack(W2[(k0 + 8) * 64 + m0],     W2[(k0 + 9) * 64 + m0]);
            afr[mt][kt][3] = bfpack(W2[(k0 + 8) * 64 + m0 + 8], W2[(k0 + 9) * 64 + m0 + 8]);
        }
    }
    // epilogue row constants
    float b2lo[4], b2hi[4], w3lo[4], w3hi[4];
    #pragma unroll
    for (int mt = 0; mt < 4; mt++) {
        b2lo[mt] = b2[16 * mt + r];     b2hi[mt] = b2[16 * mt + r + 8];
        w3lo[mt] = W3[16 * mt + r];     w3hi[mt] = W3[16 * mt + r + 8];
    }

    // layer-1 constants: lane computes h1 rows l and l+32
    const float w1a0 = W1[0 * 64 + l],      w1a1 = W1[1 * 64 + l],      w1a2 = W1[2 * 64 + l];
    const float w1b0 = W1[0 * 64 + l + 32], w1b1 = W1[1 * 64 + l + 32], w1b2 = W1[2 * 64 + l + 32];
    const float b1a = b1[l], b1b = b1[l + 32];

    const float omega = *omega_p, beta = *beta_p, tau1 = *tau1_p, tau2 = *tau2_p;
    const float gam = *gamma_p, xi = *xi_p, phi = *phi_p;
    const float d1 = *d1_p, d2 = *d2_p, mu = *mu_p, b3 = *b3_p;

    // this warp's 4 batch chains
    const long bg = (long)blockIdx.x * 32 + w * 4;
    const float* rp = returns + bg * TT;
    const float* lp = log_rv + bg * TT;
    const long BT = (long)BB * TT;

    float lh[4];
    #pragma unroll
    for (int b = 0; b < 4; b++) lh[b] = lp[b * TT];   // log(mean(exp(lrv0))) == lrv0

    u16* hw = &hsm[w][0][0];
    // b-fragment source row for this lane (chains 0-3 on lanes 0-15)
    const u16* browp = &hsm[w][r & 3][kq];
    const bool bactive = (l < 16);
    float* obw = &obuf[w][0][0];

    for (int t = 0; t < TT; t++) {
        // ---- inputs ----
        float rcur[4], lcur[4];
        #pragma unroll
        for (int b = 0; b < 4; b++) { rcur[b] = rp[b * TT + t]; lcur[b] = lp[b * TT + t]; }

        // ---- measurement (redundant in every lane, exact fp32) ----
        float z[4], u[4], z2m1[4];
        #pragma unroll
        for (int b = 0; b < 4; b++) {
            float e = __expf(-0.5f * lh[b]);
            z[b] = (rcur[b] - mu) * e;
            z2m1[b] = z[b] * z[b] - 1.0f;
            float s = xi + phi * lh[b] + d1 * z[b] + d2 * z2m1[b];
            u[b] = lcur[b] - s;              // log_x == lcur exactly
        }

        // ---- layer 1 (fp32): rows l and l+32, 4 chains ----
        float va[4], vb[4];
        #pragma unroll
        for (int b = 0; b < 4; b++) {
            float t0 = fmaf(w1a0, lh[b], b1a);
            t0 = fmaf(w1a1, z[b], t0);
            t0 = fmaf(w1a2, u[b], t0);
            va[b] = fmaxf(t0, 0.0f);
            float t1 = fmaf(w1b0, lh[b], b1b);
            t1 = fmaf(w1b1, z[b], t1);
            t1 = fmaf(w1b2, u[b], t1);
            vb[b] = fmaxf(t1, 0.0f);
        }

        // ---- h -> bf16 tile [chain][i] ----
        #pragma unroll
        for (int c = 0; c < 4; c++) {
            hw[c * 80 + l]      = bf1(va[c]);
            hw[c * 80 + l + 32] = bf1(vb[c]);
        }

        // stage reduction-independent outputs (lanes 4..15): arr 1=lx, 2=z, 3=u
        {
            const int bsel = l & 3;
            float v_lx = pick4(lcur[0], lcur[1], lcur[2], lcur[3], bsel);
            float v_z  = pick4(z[0], z[1], z[2], z[3], bsel);
            float v_u  = pick4(u[0], u[1], u[2], u[3], bsel);
            float v = pick4(v_lx, v_lx, v_z, v_u, l >> 2);
            if (l >= 4 && l < 16) obw[l * 33 + (t & 31)] = v;
        }
        __syncwarp();

        // ---- B fragments: lane l<16 -> chain r, k-pair (kq, kq+1, +8, +9) ----
        u32 bfr[4][2];
        #pragma unroll
        for (int kt = 0; kt < 4; kt++) {
            u32 b01 = 0, b23 = 0;
            if (bactive) {
                b01 = *reinterpret_cast<const u32*>(browp + 16 * kt);
                b23 = *reinterpret_cast<const u32*>(browp + 16 * kt + 8);
            }
            bfr[kt][0] = b01; bfr[kt][1] = b23;
        }

        // ---- layer 2 on tensor pipe: y = W2^T h + b2, fp32 accum ----
        float cf[4][4];
        #pragma unroll
        for (int mt = 0; mt < 4; mt++) {
            cf[mt][0] = b2lo[mt]; cf[mt][1] = b2lo[mt];
            cf[mt][2] = b2hi[mt]; cf[mt][3] = b2hi[mt];
            #pragma unroll
            for (int kt = 0; kt < 4; kt++)
                mma16816(cf[mt][0], cf[mt][1], cf[mt][2], cf[mt][3],
                         afr[mt][kt][0], afr[mt][kt][1], afr[mt][kt][2], afr[mt][kt][3],
                         bfr[kt][0], bfr[kt][1]);
        }

        // ---- layer 3 epilogue: relu + W3 dot; lane holds cols (kq, kq+1) ----
        float pe = 0.0f, po = 0.0f;
        #pragma unroll
        for (int mt = 0; mt < 4; mt++) {
            pe = fmaf(fmaxf(cf[mt][0], 0.0f), w3lo[mt], pe);
            pe = fmaf(fmaxf(cf[mt][2], 0.0f), w3hi[mt], pe);
            po = fmaf(fmaxf(cf[mt][1], 0.0f), w3lo[mt], po);
            po = fmaf(fmaxf(cf[mt][3], 0.0f), w3hi[mt], po);
        }
        u64 pair = pk2(pe, po);
        // reduce over row groups (lanes with equal l%4): xor 4, 8, 16
        #pragma unroll
        for (int s = 4; s <= 16; s <<= 1)
            pair = add2(pair, __shfl_xor_sync(0xffffffffu, pair, s));
        // broadcast chain totals: class 0 holds (tot0,tot1), class 1 (tot2,tot3)
        const int base = l & ~3;
        u64 t01 = __shfl_sync(0xffffffffu, pair, base);
        u64 t23 = __shfl_sync(0xffffffffu, pair, base + 1);
        float tot[4];
        up2(t01, tot[0], tot[1]);
        up2(t23, tot[2], tot[3]);

        float enh[4];
        #pragma unroll
        for (int b = 0; b < 4; b++)
            enh[b] = fmaf(0.01f, tot[b] + b3, lh[b]);

        if (l < 4) obw[l * 33 + (t & 31)] = enh[l];

        // ---- GARCH recurrence ----
        #pragma unroll
        for (int b = 0; b < 4; b++) {
            float nl = fmaf(beta, enh[b], omega);
            nl = fmaf(tau1, z[b], nl);
            nl = fmaf(tau2, z2m1[b], nl);
            lh[b] = fmaf(gam, u[b], nl);
        }

        // ---- coalesced flush every 32 steps (warp-private buffer) ----
        if ((t & 31) == 31) {
            const int t0 = t - 31;
            #pragma unroll
            for (int q = 0; q < 16; q++) {
                const int arr = q >> 2, bsel = q & 3;
                out[(long)arr * BT + (bg + bsel) * TT + t0 + l] = obw[q * 33 + l];
            }
        }
        __syncwarp();
    }
}

extern "C" void kernel_launch(void* const* d_in, const int* in_sizes, int n_in,
                              void* d_out, int out_size)
{
    garch_pinn_kernel<<<NCTA, NTH>>>(
        (const float*)d_in[0],  (const float*)d_in[1],
        (const float*)d_in[2],  (const float*)d_in[3],
        (const float*)d_in[4],  (const float*)d_in[5],
        (const float*)d_in[6],  (const float*)d_in[7],
        (const float*)d_in[8],  (const float*)d_in[9],
        (const float*)d_in[10], (const float*)d_in[11],
        (const float*)d_in[12], (const float*)d_in[13],
        (const float*)d_in[14], (const float*)d_in[15],
        (const float*)d_in[16], (const float*)d_in[17],
        (float*)d_out);
}